// round 1
// baseline (speedup 1.0000x reference)
#include <cuda_runtime.h>
#include <math_constants.h>

// Problem constants (fixed by the dataset)
#define BATCH   8
#define NSHAPE  8192     // shape points per batch (row stride 6, use first 3)
#define NSKEL   2048     // skel points per batch (row stride 3)
#define SSTRIDE 6

// Scratch: per-skel-point squared-distance minima (bitwise-comparable since d2>=0),
// and a single float accumulator. __device__ globals (no allocation allowed).
__device__ unsigned int g_min2[BATCH * NSKEL];
__device__ float        g_accum;

// ---------------------------------------------------------------------------
// Block-wide sum reduction (returns valid value in thread 0)
// ---------------------------------------------------------------------------
__device__ __forceinline__ float block_reduce_sum(float v) {
    __shared__ float warpsum[32];
    const int lane = threadIdx.x & 31;
    const int wid  = threadIdx.x >> 5;
#pragma unroll
    for (int o = 16; o > 0; o >>= 1) v += __shfl_down_sync(0xffffffffu, v, o);
    if (lane == 0) warpsum[wid] = v;
    __syncthreads();
    if (wid == 0) {
        const int nw = blockDim.x >> 5;
        v = (lane < nw) ? warpsum[lane] : 0.0f;
#pragma unroll
        for (int o = 16; o > 0; o >>= 1) v += __shfl_down_sync(0xffffffffu, v, o);
    }
    return v;
}

// ---------------------------------------------------------------------------
// Kernel 0: re-init scratch every launch (graph-replay deterministic)
// ---------------------------------------------------------------------------
__global__ void init_kernel() {
    const int i = blockIdx.x * blockDim.x + threadIdx.x;
    if (i == 0) g_accum = 0.0f;
    if (i < BATCH * NSKEL) g_min2[i] = 0x7F800000u;  // +inf bits
}

// ---------------------------------------------------------------------------
// Kernel 1: shape -> skel. One thread per shape point; the full skel set for
// this batch lives in shared memory (2048*3*4 = 24 KB). Inner loop is a pure
// fma-pipe min-reduction over squared distances; sqrt once at the end.
// Grid: (NSHAPE/256, BATCH), block 256.
// ---------------------------------------------------------------------------
__global__ void __launch_bounds__(256) side1_kernel(
    const float* __restrict__ shape, const float* __restrict__ skel)
{
    __shared__ float skx[NSKEL];
    __shared__ float sky[NSKEL];
    __shared__ float skz[NSKEL];

    const int b = blockIdx.y;
    const float* sk = skel + (size_t)b * NSKEL * 3;
    for (int j = threadIdx.x; j < NSKEL; j += blockDim.x) {
        skx[j] = sk[j * 3 + 0];
        sky[j] = sk[j * 3 + 1];
        skz[j] = sk[j * 3 + 2];
    }
    __syncthreads();

    const int i = blockIdx.x * blockDim.x + threadIdx.x;  // 0..NSHAPE-1
    const float* p = shape + ((size_t)b * NSHAPE + i) * SSTRIDE;
    const float px = p[0], py = p[1], pz = p[2];

    float m = CUDART_INF_F;
#pragma unroll 8
    for (int j = 0; j < NSKEL; j++) {
        const float dx = px - skx[j];
        const float dy = py - sky[j];
        const float dz = pz - skz[j];
        const float d2 = fmaf(dx, dx, fmaf(dy, dy, dz * dz));
        m = fminf(m, d2);
    }

    const float s = block_reduce_sum(sqrtf(m));
    if (threadIdx.x == 0) atomicAdd(&g_accum, s);
}

// ---------------------------------------------------------------------------
// Kernel 2: skel -> shape. Only 2048 skel points per batch, so split the
// 8192-point shape set into chunks of 1024 (12 KB smem) to get 512 blocks of
// parallelism; combine partial minima with bitwise atomicMin on uint.
// Grid: (NSKEL/256, NSHAPE/1024, BATCH), block 256.
// ---------------------------------------------------------------------------
#define TCH 1024
__global__ void __launch_bounds__(256) side2_kernel(
    const float* __restrict__ shape, const float* __restrict__ skel)
{
    __shared__ float spx[TCH];
    __shared__ float spy[TCH];
    __shared__ float spz[TCH];

    const int b     = blockIdx.z;
    const int chunk = blockIdx.y;
    const float* sp = shape + ((size_t)b * NSHAPE + chunk * TCH) * SSTRIDE;
    for (int j = threadIdx.x; j < TCH; j += blockDim.x) {
        spx[j] = sp[j * SSTRIDE + 0];
        spy[j] = sp[j * SSTRIDE + 1];
        spz[j] = sp[j * SSTRIDE + 2];
    }
    __syncthreads();

    const int k = blockIdx.x * blockDim.x + threadIdx.x;  // 0..NSKEL-1
    const float* q = skel + ((size_t)b * NSKEL + k) * 3;
    const float qx = q[0], qy = q[1], qz = q[2];

    float m = CUDART_INF_F;
#pragma unroll 8
    for (int j = 0; j < TCH; j++) {
        const float dx = qx - spx[j];
        const float dy = qy - spy[j];
        const float dz = qz - spz[j];
        const float d2 = fmaf(dx, dx, fmaf(dy, dy, dz * dz));
        m = fminf(m, d2);
    }

    // d2 >= 0 -> IEEE float bit pattern is monotone as uint
    atomicMin(&g_min2[b * NSKEL + k], __float_as_uint(m));
}

// ---------------------------------------------------------------------------
// Kernel 3: sqrt + sum the skel-side minima. Grid: (BATCH*NSKEL/256), block 256.
// ---------------------------------------------------------------------------
__global__ void __launch_bounds__(256) side2_reduce_kernel() {
    const int i = blockIdx.x * blockDim.x + threadIdx.x;
    const float m = __uint_as_float(g_min2[i]);
    const float s = block_reduce_sum(sqrtf(m));
    if (threadIdx.x == 0) atomicAdd(&g_accum, s);
}

// ---------------------------------------------------------------------------
// Kernel 4: write the scalar output
// ---------------------------------------------------------------------------
__global__ void write_out_kernel(float* __restrict__ out) {
    out[0] = g_accum * 1.0e-4f;
}

// ---------------------------------------------------------------------------
extern "C" void kernel_launch(void* const* d_in, const int* in_sizes, int n_in,
                              void* d_out, int out_size)
{
    const float* shape = (const float*)d_in[0];  // (8, 8192, 6) fp32
    const float* skel  = (const float*)d_in[1];  // (8, 2048, 3) fp32
    float* out = (float*)d_out;

    init_kernel<<<(BATCH * NSKEL + 255) / 256, 256>>>();
    side1_kernel<<<dim3(NSHAPE / 256, BATCH), 256>>>(shape, skel);
    side2_kernel<<<dim3(NSKEL / 256, NSHAPE / TCH, BATCH), 256>>>(shape, skel);
    side2_reduce_kernel<<<(BATCH * NSKEL) / 256, 256>>>();
    write_out_kernel<<<1, 1>>>(out);
}

// round 2
// speedup vs baseline: 1.7695x; 1.7695x over previous
#include <cuda_runtime.h>
#include <math_constants.h>

#define BATCH   8
#define NSHAPE  8192
#define NSKEL   2048
#define SSTRIDE 6
#define TCH     2048            // side-2 shape chunk
#define NJJ     1024            // point-pairs per tile (both sides: 2048 points)

// Scratch (no allocations allowed): per-skel-point min d2 (clamped >=0, so
// bitwise uint min is monotone), scalar accumulator, completion counter.
__device__ unsigned int g_min2[BATCH * NSKEL];
__device__ float        g_accum;
__device__ unsigned int g_count;

// ---------------------------------------------------------------------------
// packed f32x2 helpers (ptxas will not auto-fuse FFMA2 from C++)
// ---------------------------------------------------------------------------
__device__ __forceinline__ unsigned long long pack2(float v) {
    unsigned long long r;
    asm("mov.b64 %0, {%1,%2};" : "=l"(r) : "f"(v), "f"(v));
    return r;
}
__device__ __forceinline__ unsigned long long fma2(unsigned long long a,
                                                   unsigned long long b,
                                                   unsigned long long c) {
    unsigned long long d;
    asm("fma.rn.f32x2 %0, %1, %2, %3;" : "=l"(d) : "l"(a), "l"(b), "l"(c));
    return d;
}
__device__ __forceinline__ void unpack2(unsigned long long v, float& lo, float& hi) {
    asm("mov.b64 {%0,%1}, %2;" : "=f"(lo), "=f"(hi) : "l"(v));
}

__device__ __forceinline__ float block_reduce_sum(float v) {
    __shared__ float warpsum[32];
    const int lane = threadIdx.x & 31;
    const int wid  = threadIdx.x >> 5;
#pragma unroll
    for (int o = 16; o > 0; o >>= 1) v += __shfl_down_sync(0xffffffffu, v, o);
    if (lane == 0) warpsum[wid] = v;
    __syncthreads();
    if (wid == 0) {
        const int nw = blockDim.x >> 5;
        v = (lane < nw) ? warpsum[lane] : 0.0f;
#pragma unroll
        for (int o = 16; o > 0; o >>= 1) v += __shfl_down_sync(0xffffffffu, v, o);
    }
    return v;
}

// ---------------------------------------------------------------------------
// Kernel 0: re-init scratch each replay
// ---------------------------------------------------------------------------
__global__ void init_kernel() {
    const int i = blockIdx.x * blockDim.x + threadIdx.x;
    if (i == 0) { g_accum = 0.0f; g_count = 0u; }
    if (i < BATCH * NSKEL) g_min2[i] = 0x7F800000u;  // +inf
}

// ---------------------------------------------------------------------------
// Fused pair-loop kernel. 512 uniform blocks of 128 threads; each thread owns
// 2 query points and scans a 2048-point tile in smem.
//   blocks [0,256):   side1  (queries = shape pts, tile = full skel set)
//   blocks [256,512): side2  (queries = skel pts, tile = one shape chunk)
// Tile layout (pairs of points j0=2jj, j1=2jj+1):
//   sA[jj] = (x0,x1,y0,y1)   sB[jj] = (z0,z1,n0,n1)   n = x^2+y^2+z^2
// Inner loop per jj: 2x LDS.128 + 6x FFMA2 + 4x FMNMX  -> 3 instr / pair.
// t = n_j - 2 p.q_j ; d2 = max(|p|^2 + min_j t, 0)
// ---------------------------------------------------------------------------
__global__ void __launch_bounds__(128) pair_kernel(
    const float* __restrict__ shape, const float* __restrict__ skel)
{
    __shared__ float4 sA[NJJ];
    __shared__ float4 sB[NJJ];

    const int tid = threadIdx.x;
    const int bid = blockIdx.x;
    const bool side1 = (bid < 256);

    // ---- fill tile ----
    if (side1) {
        const int b = bid >> 5;                       // bid/32
        const float* sk = skel + (size_t)b * NSKEL * 3;
        for (int jj = tid; jj < NJJ; jj += 128) {
            const float* s0 = sk + jj * 6;            // two consecutive skel pts
            const float x0 = s0[0], y0 = s0[1], z0 = s0[2];
            const float x1 = s0[3], y1 = s0[4], z1 = s0[5];
            sA[jj] = make_float4(x0, x1, y0, y1);
            sB[jj] = make_float4(z0, z1,
                                 fmaf(x0, x0, fmaf(y0, y0, z0 * z0)),
                                 fmaf(x1, x1, fmaf(y1, y1, z1 * z1)));
        }
    } else {
        const int r     = bid - 256;
        const int b     = r >> 5;                     // r/32
        const int r2    = r & 31;
        const int chunk = r2 >> 3;                    // 0..3
        const float* sp = shape + ((size_t)b * NSHAPE + chunk * TCH) * SSTRIDE;
        for (int jj = tid; jj < NJJ; jj += 128) {
            const float* s0 = sp + jj * 2 * SSTRIDE;
            const float x0 = s0[0], y0 = s0[1], z0 = s0[2];
            const float x1 = s0[6], y1 = s0[7], z1 = s0[8];
            sA[jj] = make_float4(x0, x1, y0, y1);
            sB[jj] = make_float4(z0, z1,
                                 fmaf(x0, x0, fmaf(y0, y0, z0 * z0)),
                                 fmaf(x1, x1, fmaf(y1, y1, z1 * z1)));
        }
    }
    __syncthreads();

    // ---- load this thread's two query points ----
    float ax, ay, az, bx, by, bz;
    int b_batch, q0;
    if (side1) {
        b_batch = bid >> 5;
        const int ib = bid & 31;
        q0 = ib * 256 + tid;                          // and q0+128
        const float* p0 = shape + ((size_t)b_batch * NSHAPE + q0) * SSTRIDE;
        ax = p0[0]; ay = p0[1]; az = p0[2];
        const float* p1 = p0 + 128 * SSTRIDE;
        bx = p1[0]; by = p1[1]; bz = p1[2];
    } else {
        const int r  = bid - 256;
        b_batch = r >> 5;
        const int kb = r & 7;
        q0 = kb * 256 + tid;                          // and q0+128
        const float* p0 = skel + ((size_t)b_batch * NSKEL + q0) * 3;
        ax = p0[0]; ay = p0[1]; az = p0[2];
        const float* p1 = p0 + 128 * 3;
        bx = p1[0]; by = p1[1]; bz = p1[2];
    }
    const float pp0 = fmaf(ax, ax, fmaf(ay, ay, az * az));
    const float pp1 = fmaf(bx, bx, fmaf(by, by, bz * bz));
    const unsigned long long qx0 = pack2(-2.0f * ax), qy0 = pack2(-2.0f * ay), qz0 = pack2(-2.0f * az);
    const unsigned long long qx1 = pack2(-2.0f * bx), qy1 = pack2(-2.0f * by), qz1 = pack2(-2.0f * bz);

    // ---- hot loop ----
    const ulonglong2* pA = reinterpret_cast<const ulonglong2*>(sA);
    const ulonglong2* pB = reinterpret_cast<const ulonglong2*>(sB);
    float m0 = CUDART_INF_F, m1 = CUDART_INF_F;
#pragma unroll 8
    for (int jj = 0; jj < NJJ; jj++) {
        const ulonglong2 A = pA[jj];   // (x-pair, y-pair)
        const ulonglong2 B = pB[jj];   // (z-pair, n-pair)
        unsigned long long t0 = fma2(qx0, A.x, B.y);
        t0 = fma2(qy0, A.y, t0);
        t0 = fma2(qz0, B.x, t0);
        unsigned long long t1 = fma2(qx1, A.x, B.y);
        t1 = fma2(qy1, A.y, t1);
        t1 = fma2(qz1, B.x, t1);
        float lo, hi;
        unpack2(t0, lo, hi); m0 = fminf(m0, fminf(lo, hi));
        unpack2(t1, lo, hi); m1 = fminf(m1, fminf(lo, hi));
    }

    const float d2_0 = fmaxf(pp0 + m0, 0.0f);
    const float d2_1 = fmaxf(pp1 + m1, 0.0f);

    if (side1) {
        const float s = block_reduce_sum(sqrtf(d2_0) + sqrtf(d2_1));
        if (tid == 0) atomicAdd(&g_accum, s);
    } else {
        // partial min over this shape chunk; clamp commutes with min
        atomicMin(&g_min2[b_batch * NSKEL + q0],       __float_as_uint(d2_0));
        atomicMin(&g_min2[b_batch * NSKEL + q0 + 128], __float_as_uint(d2_1));
    }
}

// ---------------------------------------------------------------------------
// Kernel 2: sqrt+sum skel-side minima; last block writes the scalar output.
// ---------------------------------------------------------------------------
__global__ void __launch_bounds__(256) reduce_kernel(float* __restrict__ out) {
    const int i = blockIdx.x * blockDim.x + threadIdx.x;
    const float s = block_reduce_sum(sqrtf(__uint_as_float(g_min2[i])));
    if (threadIdx.x == 0) {
        atomicAdd(&g_accum, s);
        __threadfence();
        const unsigned int old = atomicAdd(&g_count, 1u);
        if (old == gridDim.x - 1) {
            out[0] = *((volatile float*)&g_accum) * 1.0e-4f;
        }
    }
}

// ---------------------------------------------------------------------------
extern "C" void kernel_launch(void* const* d_in, const int* in_sizes, int n_in,
                              void* d_out, int out_size)
{
    const float* shape = (const float*)d_in[0];  // (8, 8192, 6) fp32
    const float* skel  = (const float*)d_in[1];  // (8, 2048, 3) fp32
    float* out = (float*)d_out;

    init_kernel<<<(BATCH * NSKEL + 255) / 256, 256>>>();
    pair_kernel<<<512, 128>>>(shape, skel);
    reduce_kernel<<<(BATCH * NSKEL) / 256, 256>>>(out);
}

// round 3
// speedup vs baseline: 1.8217x; 1.0295x over previous
#include <cuda_runtime.h>
#include <math_constants.h>

#define BATCH    8
#define NSHAPE   8192
#define NSKEL    2048
#define SSTRIDE  6
#define TILE     512            // tile points per block
#define NJJ      (TILE / 2)     // 256 packed point-pair entries
#define NQ       4              // queries per thread
#define BLK      128
#define QG       (BLK * NQ)     // 512 queries per group

#define S1_GROUPS 128           // 8*8192/512
#define S1_CHUNKS 4             // 2048/512
#define S2_GROUPS 32            // 8*2048/512
#define S2_CHUNKS 16            // 8192/512
#define S1_BLOCKS (S1_GROUPS * S1_CHUNKS)   // 512
#define NBLOCKS   (S1_BLOCKS + S2_GROUPS * S2_CHUNKS) // 1024
#define NGROUPS   (S1_GROUPS + S2_GROUPS)   // 160
#define NKEYS     ((S1_GROUPS + S2_GROUPS) * QG)  // 81920

// All state zero-initialized at module load and RESTORED to zero by the kernel
// itself each call => single launch, deterministic graph replays, no allocs.
// Min-d2 is stored as key = ~bits(d2): bits(d2) in [0,0x7F800000] so ~bits is
// strictly decreasing => atomicMax(key) == min(d2), and key==0 is the identity.
__device__ unsigned int g_key[NKEYS];
__device__ unsigned int g_gc[NGROUPS];
__device__ unsigned int g_done;
__device__ float        g_accum;

// ---------------------------------------------------------------------------
// packed f32x2 helpers (ptxas never auto-fuses FFMA2 from C++)
// ---------------------------------------------------------------------------
__device__ __forceinline__ unsigned long long pack2(float v) {
    unsigned long long r;
    asm("mov.b64 %0, {%1,%2};" : "=l"(r) : "f"(v), "f"(v));
    return r;
}
__device__ __forceinline__ unsigned long long fma2(unsigned long long a,
                                                   unsigned long long b,
                                                   unsigned long long c) {
    unsigned long long d;
    asm("fma.rn.f32x2 %0, %1, %2, %3;" : "=l"(d) : "l"(a), "l"(b), "l"(c));
    return d;
}
__device__ __forceinline__ void unpack2(unsigned long long v, float& lo, float& hi) {
    asm("mov.b64 {%0,%1}, %2;" : "=f"(lo), "=f"(hi) : "l"(v));
}

__device__ __forceinline__ float block_reduce_sum(float v) {
    __shared__ float warpsum[BLK / 32];
    const int lane = threadIdx.x & 31;
    const int wid  = threadIdx.x >> 5;
#pragma unroll
    for (int o = 16; o > 0; o >>= 1) v += __shfl_down_sync(0xffffffffu, v, o);
    if (lane == 0) warpsum[wid] = v;
    __syncthreads();
    if (wid == 0) {
        v = (lane < (BLK / 32)) ? warpsum[lane] : 0.0f;
#pragma unroll
        for (int o = 16; o > 0; o >>= 1) v += __shfl_down_sync(0xffffffffu, v, o);
    }
    return v;
}

// ---------------------------------------------------------------------------
// Single fused kernel. 1024 uniform blocks of 128 threads.
//   blocks [0,512):    side1 — queries = shape pts, tile = 512-pt skel chunk
//   blocks [512,1024): side2 — queries = skel pts,  tile = 512-pt shape chunk
// Tile entry jj packs points j0=2jj, j1=2jj+1:
//   sA[jj]=(x0,x1,y0,y1)  sB[jj]=(z0,z1,n0,n1), n=|p|^2
// Inner loop per jj: 2 LDS.128 + 12 FFMA2 + 8 FMNMX for 8 pairs.
// t_j = n_j - 2 q.p_j ; d2 = max(|q|^2 + min_j t_j, 0); merged via atomicMax.
// ---------------------------------------------------------------------------
__global__ void __launch_bounds__(BLK) chamfer_kernel(
    const float* __restrict__ shape, const float* __restrict__ skel,
    float* __restrict__ out)
{
    __shared__ float4 sA[NJJ];
    __shared__ float4 sB[NJJ];
    __shared__ unsigned int sLast;

    const int tid = threadIdx.x;
    const int bid = blockIdx.x;
    const bool side1 = (bid < S1_BLOCKS);

    int gidx, keybase, need;
    float qxv[NQ], qyv[NQ], qzv[NQ];

    if (side1) {
        const int grp   = bid >> 2;           // 0..127
        const int chunk = bid & 3;            // 0..3
        const int b     = grp >> 4;           // 16 groups per batch
        gidx    = grp;
        keybase = grp * QG;
        need    = S1_CHUNKS;

        // tile: skel[b] points [chunk*512, chunk*512+512)
        const float* tb = skel + ((size_t)b * NSKEL + chunk * TILE) * 3;
#pragma unroll
        for (int u = 0; u < NJJ / BLK; u++) {
            const int jj = tid + u * BLK;
            const float* s0 = tb + jj * 6;
            const float x0 = s0[0], y0 = s0[1], z0 = s0[2];
            const float x1 = s0[3], y1 = s0[4], z1 = s0[5];
            sA[jj] = make_float4(x0, x1, y0, y1);
            sB[jj] = make_float4(z0, z1,
                                 fmaf(x0, x0, fmaf(y0, y0, z0 * z0)),
                                 fmaf(x1, x1, fmaf(y1, y1, z1 * z1)));
        }
        // queries: shape[b] rows (grp%16)*512 + tid + 128u
        const float* qb = shape + ((size_t)b * NSHAPE + (grp & 15) * QG + tid) * SSTRIDE;
#pragma unroll
        for (int u = 0; u < NQ; u++) {
            const float* p = qb + u * BLK * SSTRIDE;
            qxv[u] = p[0]; qyv[u] = p[1]; qzv[u] = p[2];
        }
    } else {
        const int r     = bid - S1_BLOCKS;
        const int grp   = r >> 4;             // 0..31
        const int chunk = r & 15;             // 0..15
        const int b     = grp >> 2;           // 4 groups per batch
        gidx    = S1_GROUPS + grp;
        keybase = (S1_GROUPS + grp) * QG;
        need    = S2_CHUNKS;

        // tile: shape[b] points [chunk*512, chunk*512+512) (row stride 6)
        const float* tb = shape + ((size_t)b * NSHAPE + chunk * TILE) * SSTRIDE;
#pragma unroll
        for (int u = 0; u < NJJ / BLK; u++) {
            const int jj = tid + u * BLK;
            const float* s0 = tb + jj * 2 * SSTRIDE;
            const float x0 = s0[0], y0 = s0[1], z0 = s0[2];
            const float x1 = s0[6], y1 = s0[7], z1 = s0[8];
            sA[jj] = make_float4(x0, x1, y0, y1);
            sB[jj] = make_float4(z0, z1,
                                 fmaf(x0, x0, fmaf(y0, y0, z0 * z0)),
                                 fmaf(x1, x1, fmaf(y1, y1, z1 * z1)));
        }
        // queries: skel[b] rows (grp%4)*512 + tid + 128u
        const float* qb = skel + ((size_t)b * NSKEL + (grp & 3) * QG + tid) * 3;
#pragma unroll
        for (int u = 0; u < NQ; u++) {
            const float* p = qb + u * BLK * 3;
            qxv[u] = p[0]; qyv[u] = p[1]; qzv[u] = p[2];
        }
    }
    __syncthreads();

    float pp[NQ];
    unsigned long long cx[NQ], cy[NQ], cz[NQ];
#pragma unroll
    for (int u = 0; u < NQ; u++) {
        pp[u] = fmaf(qxv[u], qxv[u], fmaf(qyv[u], qyv[u], qzv[u] * qzv[u]));
        cx[u] = pack2(-2.0f * qxv[u]);
        cy[u] = pack2(-2.0f * qyv[u]);
        cz[u] = pack2(-2.0f * qzv[u]);
    }

    // ---- hot loop: 256 iters, 8 pairs each ----
    const ulonglong2* pA = reinterpret_cast<const ulonglong2*>(sA);
    const ulonglong2* pB = reinterpret_cast<const ulonglong2*>(sB);
    float mlo[NQ], mhi[NQ];
#pragma unroll
    for (int u = 0; u < NQ; u++) { mlo[u] = CUDART_INF_F; mhi[u] = CUDART_INF_F; }

#pragma unroll 8
    for (int jj = 0; jj < NJJ; jj++) {
        const ulonglong2 A = pA[jj];   // (x-pair, y-pair)
        const ulonglong2 B = pB[jj];   // (z-pair, n-pair)
#pragma unroll
        for (int u = 0; u < NQ; u++) {
            unsigned long long t = fma2(cx[u], A.x, B.y);
            t = fma2(cy[u], A.y, t);
            t = fma2(cz[u], B.x, t);
            float lo, hi;
            unpack2(t, lo, hi);
            mlo[u] = fminf(mlo[u], lo);
            mhi[u] = fminf(mhi[u], hi);
        }
    }

    // ---- merge partial minima (key = ~bits, atomicMax, zero-identity) ----
#pragma unroll
    for (int u = 0; u < NQ; u++) {
        const float d2 = fmaxf(pp[u] + fminf(mlo[u], mhi[u]), 0.0f);
        atomicMax(&g_key[keybase + tid + u * BLK],
                  0xFFFFFFFFu ^ __float_as_uint(d2));
    }

    // ---- group completion: last chunk-block finalizes this query group ----
    __threadfence();
    __syncthreads();
    if (tid == 0) sLast = (atomicAdd(&g_gc[gidx], 1u) == (unsigned)(need - 1));
    __syncthreads();
    if (!sLast) return;
    __threadfence();

    float s = 0.0f;
#pragma unroll
    for (int u = 0; u < NQ; u++) {
        // atomicExch: L1-bypassing read + reset-to-zero for the next replay
        const unsigned int key = atomicExch(&g_key[keybase + tid + u * BLK], 0u);
        s += sqrtf(__uint_as_float(0xFFFFFFFFu ^ key));
    }
    s = block_reduce_sum(s);

    if (tid == 0) {
        g_gc[gidx] = 0;                       // reset own counter
        atomicAdd(&g_accum, s);
        __threadfence();
        if (atomicAdd(&g_done, 1u) == NGROUPS - 1) {
            out[0] = atomicExch(&g_accum, 0.0f) * 1.0e-4f;
            g_done = 0;                       // reset for next replay
        }
    }
}

// ---------------------------------------------------------------------------
extern "C" void kernel_launch(void* const* d_in, const int* in_sizes, int n_in,
                              void* d_out, int out_size)
{
    const float* shape = (const float*)d_in[0];  // (8, 8192, 6) fp32
    const float* skel  = (const float*)d_in[1];  // (8, 2048, 3) fp32
    chamfer_kernel<<<NBLOCKS, BLK>>>(shape, skel, (float*)d_out);
}